// round 7
// baseline (speedup 1.0000x reference)
#include <cuda_runtime.h>
#include <cuda_fp16.h>

#define B    4
#define CIN  3
#define COUT 16
#define H    256
#define W    256
#define K    5
#define PAD  2

// Intermediate (dilated) buffer in fp16: 8 MB.
__device__ __half g_midh[B * COUT * H * W];

// ---------------------------------------------------------------------------
// Dilation: out_d[b,o,i,j] = sum_c max_t( x[clamped win] + w_d[o,c,t] )
// Tile 32x16, 2 rows/thread packed into half2. o processed in 2 chunks of 8
// to keep live fp32 accumulators at 16 regs (occupancy).
// ---------------------------------------------------------------------------
#define DT_W 32
#define DT_H 16
#define XR (DT_H + 3)   // 19 row-pair rows
#define XC (DT_W + 4)   // 36 cols

__global__ __launch_bounds__(256) void dilate_kernel(const float* __restrict__ x,
                                                     const float* __restrict__ wd) {
    __shared__ __half2 xs2[CIN][XR][XC];        // {x[r], x[r+1]} row pairs
    __shared__ __half2 wsh[COUT * CIN * K * K]; // {w, w} replicated

    const int b      = blockIdx.z;
    const int tile_y = blockIdx.y * DT_H;
    const int tile_x = blockIdx.x * DT_W;
    const int tid    = threadIdx.y * 32 + threadIdx.x;

    for (int i = tid; i < COUT * CIN * K * K; i += 256)
        wsh[i] = __float2half2_rn(wd[i]);

    const int XN = CIN * XR * XC;
    for (int i = tid; i < XN; i += 256) {
        int c   = i / (XR * XC);
        int rem = i % (XR * XC);
        int r   = rem / XC;
        int col = rem % XC;
        int g0 = min(max(tile_y + r - PAD, 0), H - 1);
        int g1 = min(max(tile_y + r + 1 - PAD, 0), H - 1);
        int gj = min(max(tile_x + col - PAD, 0), W - 1);
        const float* xc = x + ((size_t)(b * CIN + c)) * H * W;
        xs2[c][r][col] = __floats2half2_rn(xc[g0 * W + gj], xc[g1 * W + gj]);
    }
    __syncthreads();

    const int tx  = threadIdx.x;
    const int ty  = threadIdx.y;
    const int gi0 = tile_y + ty * 2;
    const int gj  = tile_x + tx;

#pragma unroll
    for (int och = 0; och < COUT; och += 8) {
        float acc0[8], acc1[8];
#pragma unroll
        for (int o = 0; o < 8; o++) { acc0[o] = 0.0f; acc1[o] = 0.0f; }

#pragma unroll
        for (int c = 0; c < CIN; c++) {
            __half2 pv[K * K];
#pragma unroll
            for (int di = 0; di < K; di++)
#pragma unroll
                for (int dj = 0; dj < K; dj++)
                    pv[di * K + dj] = xs2[c][ty * 2 + di][tx + dj];

#pragma unroll
            for (int o = 0; o < 8; o++) {
                const __half2* w = &wsh[((och + o) * CIN + c) * (K * K)];
                __half2 m = __hadd2(pv[0], w[0]);
#pragma unroll
                for (int t = 1; t < K * K; t++)
                    m = __hmax2(m, __hadd2(pv[t], w[t]));
                float2 mf = __half22float2(m);
                acc0[o] += mf.x;
                acc1[o] += mf.y;
            }
        }

#pragma unroll
        for (int o = 0; o < 8; o++) {
            g_midh[((b * COUT + och + o) * H + gi0)     * W + gj] = __float2half(acc0[o]);
            g_midh[((b * COUT + och + o) * H + gi0 + 1) * W + gj] = __float2half(acc1[o]);
        }
    }
}

// ---------------------------------------------------------------------------
// Erosion: out = min_t( y + (-w) ), fp16 packed, 4 rows/thread.
// Fill uses 2D indexing (no div/mod), column clamp hoisted.
// ---------------------------------------------------------------------------
#define ET 32
#define YP_R (ET + 3)    // 35 pair rows
#define YP_C (ET + 4)    // 36 cols

__global__ __launch_bounds__(256) void erode_kernel(const float* __restrict__ we_g,
                                                    float* __restrict__ out) {
    __shared__ __half2 ysp[YP_R][YP_C];
    __shared__ __half2 we2[K * K];          // {-w, -w}

    const int bo     = blockIdx.z;               // b*COUT + o
    const int o      = bo % COUT;
    const int tile_y = blockIdx.y * ET;
    const int tile_x = blockIdx.x * ET;
    const int tx     = threadIdx.x;
    const int ty     = threadIdx.y;
    const int tid    = ty * 32 + tx;

    if (tid < K * K) {
        float w = we_g[o * K * K + tid];
        we2[tid] = __float2half2_rn(-w);
    }

    const __half* y = g_midh + (size_t)bo * H * W;

    // 2D fill: main 32 cols by all threads, last 4 cols by tx<4 lanes.
    {
        const int gj_main = min(max(tile_x + tx - 2, 0), W - 1);
        const int gj_tail = min(tile_x + 32 + tx - 2, W - 1);   // tile_x+30..33, >=0 always
#pragma unroll
        for (int p = ty; p < YP_R; p += 8) {
            int g0 = min(max(tile_y + p - 2, 0), H - 1);
            int g1 = min(tile_y + p - 1, H - 1);                // p-1 >= -1; p>=1 rows fine
            if (p == 0) g1 = max(tile_y - 1, 0);
            ysp[p][tx] = __halves2half2(y[g0 * W + gj_main], y[g1 * W + gj_main]);
            if (tx < 4)
                ysp[p][32 + tx] = __halves2half2(y[g0 * W + gj_tail], y[g1 * W + gj_tail]);
        }
    }
    __syncthreads();

    // Window pairs: pv[p][dj], p = 0..6 relative pair offset
    __half2 pv[7][K];
#pragma unroll
    for (int p = 0; p < 7; p++)
#pragma unroll
        for (int dj = 0; dj < K; dj++)
            pv[p][dj] = ysp[ty * 4 + p][tx + dj];

    __half2 m0 = __hadd2(pv[0][0], we2[0]);   // rows l, l+1
    __half2 m1 = __hadd2(pv[2][0], we2[0]);   // rows l+2, l+3

#pragma unroll
    for (int t = 1; t < K * K; t++) {
        const int di = t / K, dj = t % K;
        __half2 w = we2[t];
        m0 = __hmin2(m0, __hadd2(pv[di][dj],     w));
        m1 = __hmin2(m1, __hadd2(pv[di + 2][dj], w));
    }

    const int gj = tile_x + tx;
    const int gi = tile_y + ty * 4;
    float2 r01 = __half22float2(m0);
    float2 r23 = __half22float2(m1);
    float* op = out + ((size_t)bo * H + gi) * W + gj;
    op[0]     = r01.x;
    op[W]     = r01.y;
    op[2 * W] = r23.x;
    op[3 * W] = r23.y;
}

// ---------------------------------------------------------------------------
extern "C" void kernel_launch(void* const* d_in, const int* in_sizes, int n_in,
                              void* d_out, int out_size) {
    const float* x  = (const float*)d_in[0];
    const float* wd = (const float*)d_in[1];
    const float* we = (const float*)d_in[2];
    float*       out = (float*)d_out;

    dim3 bD(32, 8);
    dim3 gD(W / DT_W, H / DT_H, B);        // 8 x 16 x 4
    dilate_kernel<<<gD, bD>>>(x, wd);

    dim3 bE(32, 8);
    dim3 gE(W / ET, H / ET, B * COUT);     // 8 x 8 x 64
    erode_kernel<<<gE, bE>>>(we, out);
}

// round 8
// speedup vs baseline: 1.0548x; 1.0548x over previous
#include <cuda_runtime.h>
#include <cuda_fp16.h>

#define B    4
#define CIN  3
#define COUT 16
#define H    256
#define W    256
#define K    5
#define PAD  2
#define NP   (H / 2)      // 128 pair-rows

// Intermediate as vertical row-pairs: g_midp[bo][p][col] = {y[2p][col], y[2p+1][col]}
__device__ __half2 g_midp[B * COUT * NP * W];   // 8 MB

// odd-parity pair {a.y, b.x}
__device__ __forceinline__ __half2 oddpair(__half2 a, __half2 b) {
    unsigned r = __byte_perm(*(unsigned*)&a, *(unsigned*)&b, 0x5432);
    return *(__half2*)&r;
}

// ---------------------------------------------------------------------------
// Dilation: out_d[b,o,i,j] = sum_c max_t( x[clamped win] + w_d[o,c,t] )
// Tile 32x16, 2 rows/thread packed into half2; writes paired intermediate.
// ---------------------------------------------------------------------------
#define DT_W 32
#define DT_H 16
#define XR (DT_H + 3)   // 19 row-pair rows
#define XC (DT_W + 4)   // 36 cols

__global__ __launch_bounds__(256) void dilate_kernel(const float* __restrict__ x,
                                                     const float* __restrict__ wd) {
    __shared__ __half2 xs2[CIN][XR][XC];        // {x[r], x[r+1]} row pairs
    __shared__ __half2 wsh[COUT * CIN * K * K]; // {w, w} replicated

    const int b      = blockIdx.z;
    const int tile_y = blockIdx.y * DT_H;
    const int tile_x = blockIdx.x * DT_W;
    const int tid    = threadIdx.y * 32 + threadIdx.x;

    for (int i = tid; i < COUT * CIN * K * K; i += 256)
        wsh[i] = __float2half2_rn(wd[i]);

    const int XN = CIN * XR * XC;
    for (int i = tid; i < XN; i += 256) {
        int c   = i / (XR * XC);
        int rem = i % (XR * XC);
        int r   = rem / XC;
        int col = rem % XC;
        int g0 = min(max(tile_y + r - PAD, 0), H - 1);
        int g1 = min(max(tile_y + r + 1 - PAD, 0), H - 1);
        int gj = min(max(tile_x + col - PAD, 0), W - 1);
        const float* xc = x + ((size_t)(b * CIN + c)) * H * W;
        xs2[c][r][col] = __floats2half2_rn(xc[g0 * W + gj], xc[g1 * W + gj]);
    }
    __syncthreads();

    const int tx  = threadIdx.x;
    const int ty  = threadIdx.y;
    const int gi0 = tile_y + ty * 2;
    const int gj  = tile_x + tx;

#pragma unroll
    for (int och = 0; och < COUT; och += 8) {
        float acc0[8], acc1[8];
#pragma unroll
        for (int o = 0; o < 8; o++) { acc0[o] = 0.0f; acc1[o] = 0.0f; }

#pragma unroll
        for (int c = 0; c < CIN; c++) {
            __half2 pv[K * K];
#pragma unroll
            for (int di = 0; di < K; di++)
#pragma unroll
                for (int dj = 0; dj < K; dj++)
                    pv[di * K + dj] = xs2[c][ty * 2 + di][tx + dj];

#pragma unroll
            for (int o = 0; o < 8; o++) {
                const __half2* w = &wsh[((och + o) * CIN + c) * (K * K)];
                __half2 m = __hadd2(pv[0], w[0]);
#pragma unroll
                for (int t = 1; t < K * K; t++)
                    m = __hmax2(m, __hadd2(pv[t], w[t]));
                float2 mf = __half22float2(m);
                acc0[o] += mf.x;
                acc1[o] += mf.y;
            }
        }

        const int p = gi0 >> 1;
#pragma unroll
        for (int o = 0; o < 8; o++)
            g_midp[((b * COUT + och + o) * NP + p) * W + gj] =
                __floats2half2_rn(acc0[o], acc1[o]);
    }
}

// ---------------------------------------------------------------------------
// Erosion: out = min_t( y + (-w) ). Tile 32 cols x 64 rows, 8 rows/thread
// as 4 half2 accumulators. Even pairs from smem; odd pairs via PRMT.
// ---------------------------------------------------------------------------
#define ER_TW 32
#define ER_TH 64
#define EP_R  34         // pair rows: bases tile_y-2 .. tile_y+64 step 2
#define EP_C  36

__global__ __launch_bounds__(256) void erode_kernel(const float* __restrict__ we_g,
                                                    float* __restrict__ out) {
    __shared__ __half2 ysp[EP_R][EP_C];
    __shared__ __half2 we2[K * K];          // {-w, -w}

    const int bo     = blockIdx.z;               // b*COUT + o
    const int o      = bo % COUT;
    const int tile_y = blockIdx.y * ER_TH;
    const int tile_x = blockIdx.x * ER_TW;
    const int tx     = threadIdx.x;
    const int ty     = threadIdx.y;
    const int tid    = ty * 32 + tx;

    if (tid < K * K) {
        float w = we_g[o * K * K + tid];
        we2[tid] = __float2half2_rn(-w);
    }

    const __half2* yp = g_midp + (size_t)bo * NP * W;

    // Fill: pair row k holds rows {tile_y-2+2k, tile_y-1+2k}; global pair
    // index Pr = tile_y/2 - 1 + k. Out-of-range handled by clamp + splat.
    {
        const int gj_main = min(max(tile_x + tx - 2, 0), W - 1);
        const int gj_tail = min(tile_x + 32 + tx - 2, W - 1);
        const int Pbase   = (tile_y >> 1) - 1;
#pragma unroll
        for (int k = ty; k < EP_R; k += 8) {
            int Pr = Pbase + k;
            int P  = min(max(Pr, 0), NP - 1);
            __half2 v = yp[P * W + gj_main];
            if (Pr < 0)      v = __half2half2(__low2half(v));
            if (Pr > NP - 1) v = __half2half2(__high2half(v));
            ysp[k][tx] = v;
            if (tx < 4) {
                __half2 v2 = yp[P * W + gj_tail];
                if (Pr < 0)      v2 = __half2half2(__low2half(v2));
                if (Pr > NP - 1) v2 = __half2half2(__high2half(v2));
                ysp[k][32 + tx] = v2;
            }
        }
    }
    __syncthreads();

    const unsigned short HINF = 0x7C00;           // +inf in fp16
    __half2 m0 = __half2half2(__ushort_as_half(HINF));
    __half2 m1 = m0, m2 = m0, m3 = m0;

    const int pw = ty * 4;                        // local pair base

#pragma unroll
    for (int dj = 0; dj < K; dj++) {
        __half2 E0 = ysp[pw + 0][tx + dj];
        __half2 E1 = ysp[pw + 1][tx + dj];
        __half2 E2 = ysp[pw + 2][tx + dj];
        __half2 E3 = ysp[pw + 3][tx + dj];
        __half2 E4 = ysp[pw + 4][tx + dj];
        __half2 E5 = ysp[pw + 5][tx + dj];
        __half2 O0 = oddpair(E0, E1);
        __half2 O1 = oddpair(E1, E2);
        __half2 O2 = oddpair(E2, E3);
        __half2 O3 = oddpair(E3, E4);
        __half2 O4 = oddpair(E4, E5);

        __half2 w;
        // di = 0 (even, offset 0)
        w  = we2[0 * K + dj];
        m0 = __hmin2(m0, __hadd2(E0, w));
        m1 = __hmin2(m1, __hadd2(E1, w));
        m2 = __hmin2(m2, __hadd2(E2, w));
        m3 = __hmin2(m3, __hadd2(E3, w));
        // di = 1 (odd, offset 0)
        w  = we2[1 * K + dj];
        m0 = __hmin2(m0, __hadd2(O0, w));
        m1 = __hmin2(m1, __hadd2(O1, w));
        m2 = __hmin2(m2, __hadd2(O2, w));
        m3 = __hmin2(m3, __hadd2(O3, w));
        // di = 2 (even, offset 1)
        w  = we2[2 * K + dj];
        m0 = __hmin2(m0, __hadd2(E1, w));
        m1 = __hmin2(m1, __hadd2(E2, w));
        m2 = __hmin2(m2, __hadd2(E3, w));
        m3 = __hmin2(m3, __hadd2(E4, w));
        // di = 3 (odd, offset 1)
        w  = we2[3 * K + dj];
        m0 = __hmin2(m0, __hadd2(O1, w));
        m1 = __hmin2(m1, __hadd2(O2, w));
        m2 = __hmin2(m2, __hadd2(O3, w));
        m3 = __hmin2(m3, __hadd2(O4, w));
        // di = 4 (even, offset 2)
        w  = we2[4 * K + dj];
        m0 = __hmin2(m0, __hadd2(E2, w));
        m1 = __hmin2(m1, __hadd2(E3, w));
        m2 = __hmin2(m2, __hadd2(E4, w));
        m3 = __hmin2(m3, __hadd2(E5, w));
    }

    const int gi = tile_y + ty * 8;
    float* op = out + ((size_t)bo * H + gi) * W + tile_x + tx;
    float2 r;
    r = __half22float2(m0); op[0 * W] = r.x; op[1 * W] = r.y;
    r = __half22float2(m1); op[2 * W] = r.x; op[3 * W] = r.y;
    r = __half22float2(m2); op[4 * W] = r.x; op[5 * W] = r.y;
    r = __half22float2(m3); op[6 * W] = r.x; op[7 * W] = r.y;
}

// ---------------------------------------------------------------------------
extern "C" void kernel_launch(void* const* d_in, const int* in_sizes, int n_in,
                              void* d_out, int out_size) {
    const float* x  = (const float*)d_in[0];
    const float* wd = (const float*)d_in[1];
    const float* we = (const float*)d_in[2];
    float*       out = (float*)d_out;

    dim3 bD(32, 8);
    dim3 gD(W / DT_W, H / DT_H, B);          // 8 x 16 x 4
    dilate_kernel<<<gD, bD>>>(x, wd);

    dim3 bE(32, 8);
    dim3 gE(W / ER_TW, H / ER_TH, B * COUT); // 8 x 4 x 64
    erode_kernel<<<gE, bE>>>(we, out);
}

// round 9
// speedup vs baseline: 1.1536x; 1.0937x over previous
#include <cuda_runtime.h>
#include <cuda_fp16.h>

#define B    4
#define CIN  3
#define COUT 16
#define H    256
#define W    256
#define K    5
#define PAD  2
#define NP   (H / 2)      // 128 pair-rows

// Intermediate as vertical row-pairs: g_midp[bo][p][col] = {y[2p][col], y[2p+1][col]}
__device__ __half2 g_midp[B * COUT * NP * W];   // 8 MB

// odd-parity pair {a.y, b.x}
__device__ __forceinline__ __half2 oddpair(__half2 a, __half2 b) {
    unsigned r = __byte_perm(*(unsigned*)&a, *(unsigned*)&b, 0x5432);
    return *(__half2*)&r;
}

// ---------------------------------------------------------------------------
// Dilation: out_d[b,o,i,j] = sum_c max_t( x[clamped win] + w_d[o,c,t] )
// Tile 32x32, 4 rows/thread (2 even half2 pairs). Odd-row pairs via PRMT.
// Weight LDS amortized over 4 rows. fp32 accumulation.
// ---------------------------------------------------------------------------
#define DT_W 32
#define DT_H 32
#define DXR 18          // even pair rows: tile_y-2 .. tile_y+33
#define DXC (DT_W + 4)  // 36 cols

__global__ __launch_bounds__(256) void dilate_kernel(const float* __restrict__ x,
                                                     const float* __restrict__ wd) {
    __shared__ __half2 xs2[CIN][DXR][DXC];      // even row pairs {x[2p], x[2p+1]}
    __shared__ __half2 wsh[COUT * CIN * K * K]; // {w, w} replicated

    const int b      = blockIdx.z;
    const int tile_y = blockIdx.y * DT_H;
    const int tile_x = blockIdx.x * DT_W;
    const int tid    = threadIdx.y * 32 + threadIdx.x;

    for (int i = tid; i < COUT * CIN * K * K; i += 256)
        wsh[i] = __float2half2_rn(wd[i]);

    // fill even pairs: pair k = rows {tile_y-2+2k, tile_y-1+2k}, clamped
    const int XN = CIN * DXR * DXC;
    for (int i = tid; i < XN; i += 256) {
        int c   = i / (DXR * DXC);
        int rem = i % (DXR * DXC);
        int k   = rem / DXC;
        int col = rem % DXC;
        int r0 = min(max(tile_y - 2 + 2 * k, 0), H - 1);
        int r1 = min(max(tile_y - 1 + 2 * k, 0), H - 1);
        int gj = min(max(tile_x + col - PAD, 0), W - 1);
        const float* xc = x + ((size_t)(b * CIN + c)) * H * W;
        xs2[c][k][col] = __floats2half2_rn(xc[r0 * W + gj], xc[r1 * W + gj]);
    }
    __syncthreads();

    const int tx = threadIdx.x;
    const int ty = threadIdx.y;
    const int gj = tile_x + tx;
    const int p0 = (tile_y >> 1) + ty * 2;      // global pair of output pair A

    const __half2 NEGINF2 = __half2half2(__ushort_as_half((unsigned short)0xFC00));

#pragma unroll
    for (int och = 0; och < COUT; och += 8) {
        float aA0[8], aA1[8], aB0[8], aB1[8];
#pragma unroll
        for (int o = 0; o < 8; o++) { aA0[o] = aA1[o] = aB0[o] = aB1[o] = 0.0f; }

#pragma unroll
        for (int c = 0; c < CIN; c++) {
            __half2 mA[8], mB[8];
#pragma unroll
            for (int o = 0; o < 8; o++) { mA[o] = NEGINF2; mB[o] = NEGINF2; }

#pragma unroll
            for (int dj = 0; dj < K; dj++) {
                __half2 E0 = xs2[c][ty * 2 + 0][tx + dj];
                __half2 E1 = xs2[c][ty * 2 + 1][tx + dj];
                __half2 E2 = xs2[c][ty * 2 + 2][tx + dj];
                __half2 E3 = xs2[c][ty * 2 + 3][tx + dj];
                __half2 O0 = oddpair(E0, E1);
                __half2 O1 = oddpair(E1, E2);
                __half2 O2 = oddpair(E2, E3);

#pragma unroll
                for (int o = 0; o < 8; o++) {
                    const __half2* w = &wsh[((och + o) * CIN + c) * (K * K) + dj];
                    __half2 w0 = w[0];
                    __half2 w1 = w[K];
                    __half2 w2 = w[2 * K];
                    __half2 w3 = w[3 * K];
                    __half2 w4 = w[4 * K];
                    // pair A (rows gr0, gr0+1)
                    mA[o] = __hmax2(mA[o], __hadd2(E0, w0));
                    mA[o] = __hmax2(mA[o], __hadd2(O0, w1));
                    mA[o] = __hmax2(mA[o], __hadd2(E1, w2));
                    mA[o] = __hmax2(mA[o], __hadd2(O1, w3));
                    mA[o] = __hmax2(mA[o], __hadd2(E2, w4));
                    // pair B (rows gr0+2, gr0+3)
                    mB[o] = __hmax2(mB[o], __hadd2(E1, w0));
                    mB[o] = __hmax2(mB[o], __hadd2(O1, w1));
                    mB[o] = __hmax2(mB[o], __hadd2(E2, w2));
                    mB[o] = __hmax2(mB[o], __hadd2(O2, w3));
                    mB[o] = __hmax2(mB[o], __hadd2(E3, w4));
                }
            }

#pragma unroll
            for (int o = 0; o < 8; o++) {
                float2 fA = __half22float2(mA[o]);
                float2 fB = __half22float2(mB[o]);
                aA0[o] += fA.x; aA1[o] += fA.y;
                aB0[o] += fB.x; aB1[o] += fB.y;
            }
        }

#pragma unroll
        for (int o = 0; o < 8; o++) {
            __half2* dst = &g_midp[((b * COUT + och + o) * NP + p0) * W + gj];
            dst[0] = __floats2half2_rn(aA0[o], aA1[o]);
            dst[W] = __floats2half2_rn(aB0[o], aB1[o]);
        }
    }
}

// ---------------------------------------------------------------------------
// Erosion: out = min_t( y + (-w) ). Tile 32 cols x 64 rows, 8 rows/thread
// as 4 half2 accumulators. Even pairs from smem; odd pairs via PRMT.
// ---------------------------------------------------------------------------
#define ER_TW 32
#define ER_TH 64
#define EP_R  34
#define EP_C  36

__global__ __launch_bounds__(256) void erode_kernel(const float* __restrict__ we_g,
                                                    float* __restrict__ out) {
    __shared__ __half2 ysp[EP_R][EP_C];
    __shared__ __half2 we2[K * K];          // {-w, -w}

    const int bo     = blockIdx.z;
    const int o      = bo % COUT;
    const int tile_y = blockIdx.y * ER_TH;
    const int tile_x = blockIdx.x * ER_TW;
    const int tx     = threadIdx.x;
    const int ty     = threadIdx.y;
    const int tid    = ty * 32 + tx;

    if (tid < K * K) {
        float w = we_g[o * K * K + tid];
        we2[tid] = __float2half2_rn(-w);
    }

    const __half2* yp = g_midp + (size_t)bo * NP * W;

    {
        const int gj_main = min(max(tile_x + tx - 2, 0), W - 1);
        const int gj_tail = min(tile_x + 32 + tx - 2, W - 1);
        const int Pbase   = (tile_y >> 1) - 1;
#pragma unroll
        for (int k = ty; k < EP_R; k += 8) {
            int Pr = Pbase + k;
            int P  = min(max(Pr, 0), NP - 1);
            __half2 v = yp[P * W + gj_main];
            if (Pr < 0)      v = __half2half2(__low2half(v));
            if (Pr > NP - 1) v = __half2half2(__high2half(v));
            ysp[k][tx] = v;
            if (tx < 4) {
                __half2 v2 = yp[P * W + gj_tail];
                if (Pr < 0)      v2 = __half2half2(__low2half(v2));
                if (Pr > NP - 1) v2 = __half2half2(__high2half(v2));
                ysp[k][32 + tx] = v2;
            }
        }
    }
    __syncthreads();

    __half2 m0 = __half2half2(__ushort_as_half((unsigned short)0x7C00));
    __half2 m1 = m0, m2 = m0, m3 = m0;

    const int pw = ty * 4;

#pragma unroll
    for (int dj = 0; dj < K; dj++) {
        __half2 E0 = ysp[pw + 0][tx + dj];
        __half2 E1 = ysp[pw + 1][tx + dj];
        __half2 E2 = ysp[pw + 2][tx + dj];
        __half2 E3 = ysp[pw + 3][tx + dj];
        __half2 E4 = ysp[pw + 4][tx + dj];
        __half2 E5 = ysp[pw + 5][tx + dj];
        __half2 O0 = oddpair(E0, E1);
        __half2 O1 = oddpair(E1, E2);
        __half2 O2 = oddpair(E2, E3);
        __half2 O3 = oddpair(E3, E4);
        __half2 O4 = oddpair(E4, E5);

        __half2 w;
        w  = we2[0 * K + dj];
        m0 = __hmin2(m0, __hadd2(E0, w));
        m1 = __hmin2(m1, __hadd2(E1, w));
        m2 = __hmin2(m2, __hadd2(E2, w));
        m3 = __hmin2(m3, __hadd2(E3, w));
        w  = we2[1 * K + dj];
        m0 = __hmin2(m0, __hadd2(O0, w));
        m1 = __hmin2(m1, __hadd2(O1, w));
        m2 = __hmin2(m2, __hadd2(O2, w));
        m3 = __hmin2(m3, __hadd2(O3, w));
        w  = we2[2 * K + dj];
        m0 = __hmin2(m0, __hadd2(E1, w));
        m1 = __hmin2(m1, __hadd2(E2, w));
        m2 = __hmin2(m2, __hadd2(E3, w));
        m3 = __hmin2(m3, __hadd2(E4, w));
        w  = we2[3 * K + dj];
        m0 = __hmin2(m0, __hadd2(O1, w));
        m1 = __hmin2(m1, __hadd2(O2, w));
        m2 = __hmin2(m2, __hadd2(O3, w));
        m3 = __hmin2(m3, __hadd2(O4, w));
        w  = we2[4 * K + dj];
        m0 = __hmin2(m0, __hadd2(E2, w));
        m1 = __hmin2(m1, __hadd2(E3, w));
        m2 = __hmin2(m2, __hadd2(E4, w));
        m3 = __hmin2(m3, __hadd2(E5, w));
    }

    const int gi = tile_y + ty * 8;
    float* op = out + ((size_t)bo * H + gi) * W + tile_x + tx;
    float2 r;
    r = __half22float2(m0); op[0 * W] = r.x; op[1 * W] = r.y;
    r = __half22float2(m1); op[2 * W] = r.x; op[3 * W] = r.y;
    r = __half22float2(m2); op[4 * W] = r.x; op[5 * W] = r.y;
    r = __half22float2(m3); op[6 * W] = r.x; op[7 * W] = r.y;
}

// ---------------------------------------------------------------------------
extern "C" void kernel_launch(void* const* d_in, const int* in_sizes, int n_in,
                              void* d_out, int out_size) {
    const float* x  = (const float*)d_in[0];
    const float* wd = (const float*)d_in[1];
    const float* we = (const float*)d_in[2];
    float*       out = (float*)d_out;

    dim3 bD(32, 8);
    dim3 gD(W / DT_W, H / DT_H, B);          // 8 x 8 x 4
    dilate_kernel<<<gD, bD>>>(x, wd);

    dim3 bE(32, 8);
    dim3 gE(W / ER_TW, H / ER_TH, B * COUT); // 8 x 4 x 64
    erode_kernel<<<gE, bE>>>(we, out);
}